// round 15
// baseline (speedup 1.0000x reference)
#include <cuda_runtime.h>
#include <cuda_bf16.h>
#include <cstdint>

#define Hdim 64
#define Wdim 64
#define Bn   8
#define HIDc 32
#define Tn   16
#define CINx 16

#define PLANE 4224        // 66 rows x 64 bf16 per shifted plane

using u32 = unsigned int;
using u64 = unsigned long long;

// ---------------- persistent device scratch (no allocation) ----------------
__device__ float g_c0[(size_t)Bn * HIDc * 4096];
__device__ float g_c1[(size_t)Bn * HIDc * 4096];
// x input: [T*B*CIN][3 shifts][66][64] bf16, hi and lo planes.
__device__ __align__(128) __nv_bfloat16 g_xph[(size_t)Tn * Bn * CINx * 3 * PLANE];
__device__ __align__(128) __nv_bfloat16 g_xpl[(size_t)Tn * Bn * CINx * 3 * PLANE];
// hidden states: [parity][B*HID][3][66][64]
__device__ __align__(128) __nv_bfloat16 g_h0ph[2][(size_t)Bn * HIDc * 3 * PLANE];
__device__ __align__(128) __nv_bfloat16 g_h0pl[2][(size_t)Bn * HIDc * 3 * PLANE];
__device__ __align__(128) __nv_bfloat16 g_h1ph[2][(size_t)Bn * HIDc * 3 * PLANE];
__device__ __align__(128) __nv_bfloat16 g_h1pl[2][(size_t)Bn * HIDc * 3 * PLANE];
// weights [k][n] gate-interleaved, hi/lo
__device__ __align__(128) __nv_bfloat16 g_w0h[448 * 128], g_w0l[448 * 128];
__device__ __align__(128) __nv_bfloat16 g_w1h[576 * 128], g_w1l[576 * 128];
// permanently-zero 256B source for padded/t0 rows (device globals are zero-init).
__device__ __align__(128) __nv_bfloat16 g_zero[128];

__device__ __forceinline__ float sigm(float v) {
    return __fdividef(1.0f, 1.0f + __expf(-v));
}
__device__ __forceinline__ float tanh_fast(float v) {
    return 2.0f * sigm(2.0f * v) - 1.0f;
}
__device__ __forceinline__ u32 smem_u32(const void* p) {
    u32 a;
    asm("{ .reg .u64 t; cvta.to.shared.u64 t, %1; cvt.u32.u64 %0, t; }"
        : "=r"(a) : "l"(p));
    return a;
}
__device__ __forceinline__ void ldsm4t(u32* r, u32 addr) {
    asm volatile("ldmatrix.sync.aligned.m8n8.x4.trans.shared.b16 {%0,%1,%2,%3}, [%4];"
                 : "=r"(r[0]), "=r"(r[1]), "=r"(r[2]), "=r"(r[3]) : "r"(addr));
}
__device__ __forceinline__ void mma16816(float* d, const u32* a, const u32* b) {
    asm volatile(
        "mma.sync.aligned.m16n8k16.row.col.f32.bf16.bf16.f32 "
        "{%0,%1,%2,%3}, {%4,%5,%6,%7}, {%8,%9}, {%0,%1,%2,%3};"
        : "+f"(d[0]), "+f"(d[1]), "+f"(d[2]), "+f"(d[3])
        : "r"(a[0]), "r"(a[1]), "r"(a[2]), "r"(a[3]), "r"(b[0]), "r"(b[1]));
}
// Bulk copy global->shared, completion counted on mbarrier.
__device__ __forceinline__ void bulkN(u32 dst, const void* src, u32 bytes, u32 mbar) {
    asm volatile(
        "cp.async.bulk.shared::cta.global.mbarrier::complete_tx::bytes [%0], [%1], %2, [%3];"
        :: "r"(dst), "l"(src), "r"(bytes), "r"(mbar) : "memory");
}
__device__ __forceinline__ void mbar_arrive_tx(u32 mbar, u32 bytes) {
    asm volatile("mbarrier.arrive.expect_tx.shared::cta.b64 _, [%0], %1;"
                 :: "r"(mbar), "r"(bytes) : "memory");
}
__device__ __forceinline__ void mbar_wait(u32 addr, u32 parity) {
    asm volatile(
        "{\n\t.reg .pred P;\n\t"
        "W%=:\n\t"
        "mbarrier.try_wait.parity.acquire.cta.shared::cta.b64 P, [%0], %1, 0x989680;\n\t"
        "@!P bra W%=;\n\t}"
        :: "r"(addr), "r"(parity) : "memory");
}

// ---------------- prepass kernels ----------------
__global__ void build_x_planes(const float* __restrict__ x)
{
    size_t i = (size_t)blockIdx.x * blockDim.x + threadIdx.x;
    const size_t N = (size_t)Tn * Bn * CINx * 4096;
    if (i >= N) return;
    const size_t pi = i >> 12;           // (t*B+b)*CIN+ci
    const int px = (int)(i & 4095);
    const int y = px >> 6, xx = px & 63;
    const float v = x[i];
    const __nv_bfloat16 hh = __float2bfloat16(v);
    const __nv_bfloat16 hl = __float2bfloat16(v - __bfloat162float(hh));
    const size_t base = pi * 3 * PLANE + (size_t)(y + 1) * 64;
#pragma unroll
    for (int s = 0; s < 3; s++) {
        const int c = xx + 1 - s;
        if (c >= 0 && c < 64) {
            g_xph[base + (size_t)s * PLANE + c] = hh;
            g_xpl[base + (size_t)s * PLANE + c] = hl;
        }
    }
}

template<int LAYER>
__global__ void split_w_kernel(const float* __restrict__ Wt)
{
    constexpr int KLOG = (LAYER ? (HIDc + HIDc) : (CINx + HIDc)) * 9;   // 576 / 432
    constexpr int KPAD = LAYER ? 576 : 448;
    __nv_bfloat16* wh = LAYER ? g_w1h : g_w0h;
    __nv_bfloat16* wl = LAYER ? g_w1l : g_w0l;
    int idx = blockIdx.x * blockDim.x + threadIdx.x;
    if (idx < KPAD * 128) {
        int k = idx >> 7, n = idx & 127;
        int oc = (n & 3) * HIDc + (n >> 2);      // n = hc*4 + gate
        float v = (k < KLOG) ? Wt[(size_t)oc * KLOG + k] : 0.0f;
        __nv_bfloat16 h = __float2bfloat16(v);
        wh[idx] = h;
        wl[idx] = __float2bfloat16(v - __bfloat162float(h));
    }
}

// ---------------- main step kernel ----------------
#define RSTRB 272                 // bytes per A smem k-row (128 px *2B + 16B pad)
#define BSTRB 144                 // bytes per B smem k-row (64 oc *2B + 16B pad)
#define ATILEU (32 * 68)          // u32 per A tile
#define BTILEU (32 * 36)          // u32 per B tile
#define BUFU  (2 * ATILEU + 2 * BTILEU)   // 6656 u32 = 26624 B
#define NBUF  2
#define SMEM_DYN (NBUF * BUFU * 4)        // 53248 B

// Buffer layout: [Ah][Al][Bh][Bl]
// Block: M=128 px (2 y-rows) x N=64 oc (half selected by blockIdx.z).
// Warp tile: 32 px x 32 oc. 3 blocks/SM.
template<int CIN_X, int LAYER>
__global__ __launch_bounds__(256, 3)
void step_mma(const float* __restrict__ bias,
              float* __restrict__ h_out,     // fp32 h_seq slab for this t
              int t)
{
    constexpr int CIN_TOT = CIN_X + HIDc;
    constexpr int KLOG = CIN_TOT * 9;
    constexpr int NCH  = (KLOG + 31) / 32;    // 14 / 18

    extern __shared__ __align__(128) u32 dsm[];
    __shared__ float sb[128];
    __shared__ __align__(8) u64 s_mbar[NBUF];

    const int tid = threadIdx.x;
    const int l = tid & 31;
    const int w = tid >> 5;
    const int b = blockIdx.y;
    const int y0 = blockIdx.x * 2;
    const int nsel = blockIdx.z;              // 0/1: which 64-oc half
    const int t0 = (t == 0);
    float* c_state = LAYER ? g_c1 : g_c0;
    __nv_bfloat16* hph = LAYER ? g_h1ph[t & 1] : g_h0ph[t & 1];
    __nv_bfloat16* hpl = LAYER ? g_h1pl[t & 1] : g_h0pl[t & 1];

    if (tid < 128) {
        const int hc = tid >> 2, g = tid & 3;
        sb[tid] = bias[g * HIDc + hc];
    }
    u32 mb[NBUF];
#pragma unroll
    for (int s = 0; s < NBUF; s++) mb[s] = smem_u32(&s_mbar[s]);
    if (tid == 0) {
#pragma unroll
        for (int s = 0; s < NBUF; s++)
            asm volatile("mbarrier.init.shared.b64 [%0], 128;" :: "r"(mb[s]) : "memory");
    }
    __syncthreads();

    // warp tile: wm in {0,32,64,96}, wn in {0,32}
    const int wm = (w & 3) * 32;
    const int wn = (w >> 2) * 32;

    const u32 smb = smem_u32(dsm);
    // ldmatrix lane base offsets (bytes)
    const u32 aLane = (u32)(((l & 7) + ((l >> 4) & 1) * 8) * RSTRB + ((l >> 3) & 1) * 16);
    const u32 bLane = (u32)(((l & 7) + ((l >> 3) & 1) * 8) * BSTRB + ((l >> 4) & 1) * 16);

    float acc[2][4][4];
#pragma unroll
    for (int mi = 0; mi < 2; mi++)
#pragma unroll
        for (int ni = 0; ni < 4; ni++)
#pragma unroll
            for (int q = 0; q < 4; q++) acc[mi][ni][q] = 0.0f;

    // ---------------- staging: 64x256B (A) + 64x128B (B) bulk copies ----------
    auto stage = [&](int ch, int buf) {
        if (tid >= 128) return;
        const u32 mbar = mb[buf];
        const int grp  = tid >> 6;          // 0 = A, 1 = B
        const int tsel = (tid >> 5) & 1;    // 0 = hi, 1 = lo
        const int kr   = tid & 31;
        if (grp == 0) {
            const int k = ch * 32 + kr;
            int ci = k / 9;
            const int rem = k - ci * 9;
            const int ky = rem / 3;          // 0..2
            int s = rem - ky * 3;            // kx+1
            bool zero = (k >= KLOG);
            if (zero) { ci = 0; s = 0; }
            const __nv_bfloat16* plane;
            if (LAYER == 0) {
                if (ci < CIN_X) {
                    const size_t pi = ((size_t)((t * Bn + b) * CINx + ci) * 3 + s) * PLANE;
                    plane = (tsel ? g_xpl : g_xph) + pi;
                } else {
                    if (t0) zero = true;
                    const size_t pi = ((size_t)(b * HIDc + (ci - CIN_X)) * 3 + s) * PLANE;
                    plane = (tsel ? g_h0pl[(t + 1) & 1] : g_h0ph[(t + 1) & 1]) + pi;
                }
            } else {
                if (ci < HIDc) {
                    const size_t pi = ((size_t)(b * HIDc + ci) * 3 + s) * PLANE;
                    plane = (tsel ? g_h0pl[t & 1] : g_h0ph[t & 1]) + pi;
                } else {
                    if (t0) zero = true;
                    const size_t pi = ((size_t)(b * HIDc + (ci - HIDc)) * 3 + s) * PLANE;
                    plane = (tsel ? g_h1pl[(t + 1) & 1] : g_h1ph[(t + 1) & 1]) + pi;
                }
            }
            const __nv_bfloat16* src = zero ? g_zero : (plane + (size_t)(y0 + ky) * 64);
            const u32 dst = smb + (u32)(buf * BUFU + tsel * ATILEU) * 4u + (u32)(kr * RSTRB);
            mbar_arrive_tx(mbar, 256);
            bulkN(dst, src, 256, mbar);
        } else {
            const __nv_bfloat16* wp = LAYER ? (tsel ? g_w1l : g_w1h)
                                            : (tsel ? g_w0l : g_w0h);
            const __nv_bfloat16* src = wp + (size_t)(ch * 32 + kr) * 128 + nsel * 64;
            const u32 dst = smb + (u32)(buf * BUFU + 2 * ATILEU + tsel * BTILEU) * 4u
                                + (u32)(kr * BSTRB);
            mbar_arrive_tx(mbar, 128);
            bulkN(dst, src, 128, mbar);
        }
    };

    // ---------------- compute: fragment-reuse split passes ----------
    auto compute = [&](int buf) {
        const u32 Ah = smb + (u32)(buf * BUFU) * 4u;
        const u32 Al = Ah + (u32)ATILEU * 4u;
        const u32 Bh = Al + (u32)ATILEU * 4u;
        const u32 Bl = Bh + (u32)BTILEU * 4u;
#pragma unroll
        for (int k16 = 0; k16 < 2; k16++) {
            const u32 kofA = (u32)(k16 * 16 * RSTRB);
            const u32 kofB = (u32)(k16 * 16 * BSTRB);
            u32 ah0[4], ah1[4], al0[4], al1[4];
            ldsm4t(ah0, Ah + kofA + aLane + (u32)(wm * 2));
            ldsm4t(ah1, Ah + kofA + aLane + (u32)((wm + 16) * 2));
            ldsm4t(al0, Al + kofA + aLane + (u32)(wm * 2));
            ldsm4t(al1, Al + kofA + aLane + (u32)((wm + 16) * 2));
            u32 bb[8];
            ldsm4t(bb + 0, Bh + kofB + bLane + (u32)(wn * 2));
            ldsm4t(bb + 4, Bh + kofB + bLane + (u32)((wn + 16) * 2));
#pragma unroll
            for (int ni = 0; ni < 4; ni++) {
                const u32* bf = &bb[(ni >> 1) * 4 + (ni & 1) * 2];
                mma16816(acc[0][ni], ah0, bf);
                mma16816(acc[1][ni], ah1, bf);
            }
#pragma unroll
            for (int ni = 0; ni < 4; ni++) {
                const u32* bf = &bb[(ni >> 1) * 4 + (ni & 1) * 2];
                mma16816(acc[0][ni], al0, bf);
                mma16816(acc[1][ni], al1, bf);
            }
            ldsm4t(bb + 0, Bl + kofB + bLane + (u32)(wn * 2));
            ldsm4t(bb + 4, Bl + kofB + bLane + (u32)((wn + 16) * 2));
#pragma unroll
            for (int ni = 0; ni < 4; ni++) {
                const u32* bf = &bb[(ni >> 1) * 4 + (ni & 1) * 2];
                mma16816(acc[0][ni], ah0, bf);
                mma16816(acc[1][ni], ah1, bf);
            }
        }
    };

    // ---------------- pipelined chunk loop (R13 structure) ----------------
    int ph[NBUF] = {0, 0};
    stage(0, 0);
    for (int c = 0; c < NCH; c++) {
        __syncthreads();                       // all warps done with buf (c+1)&1
        if (c + 1 < NCH) stage(c + 1, (c + 1) & 1);
        const int s = c & 1;
        mbar_wait(mb[s], ph[s]);
        ph[s] ^= 1;
        compute(s);
    }

    // ---------------- epilogue: gate math + h plane writes -------
    const int tig = l & 3;
    const int rr = l >> 2;
#pragma unroll
    for (int mi = 0; mi < 2; mi++) {
#pragma unroll
        for (int ni = 0; ni < 4; ni++) {
            float* d = acc[mi][ni];
            const float s0 = (tig & 1) ? d[0] : d[2];
            const float s1 = (tig & 1) ? d[1] : d[3];
            const float r0 = __shfl_xor_sync(0xffffffffu, s0, 1);
            const float r1 = __shfl_xor_sync(0xffffffffu, s1, 1);
            float iv, fv, ov, gv;
            int px;
            if (tig & 1) { iv = r0; fv = r1; ov = d[2]; gv = d[3]; px = wm + mi * 16 + rr + 8; }
            else         { iv = d[0]; fv = d[1]; ov = r0; gv = r1; px = wm + mi * 16 + rr; }
            const int hc = ((nsel * 64 + wn + ni * 8) >> 2) + (tig >> 1);
            iv += sb[hc * 4 + 0];
            fv += sb[hc * 4 + 1];
            ov += sb[hc * 4 + 2];
            gv += sb[hc * 4 + 3];
            const int yy = y0 + (px >> 6);
            const int xx = px & 63;
            const size_t off = (((size_t)b * HIDc + hc) * Hdim + yy) * Wdim + xx;
            const float cp = t0 ? 0.0f : c_state[off];
            const float cn = sigm(fv) * cp + sigm(iv) * tanh_fast(gv);
            const float hn = sigm(ov) * tanh_fast(cn);
            c_state[off] = cn;
            h_out[off] = hn;
            const __nv_bfloat16 hh = __float2bfloat16(hn);
            const __nv_bfloat16 hl = __float2bfloat16(hn - __bfloat162float(hh));
            const size_t pb = (size_t)(b * HIDc + hc) * 3 * PLANE + (size_t)(yy + 1) * 64;
#pragma unroll
            for (int s2 = 0; s2 < 3; s2++) {
                const int cc = xx + 1 - s2;
                if (cc >= 0 && cc < 64) {
                    hph[pb + (size_t)s2 * PLANE + cc] = hh;
                    hpl[pb + (size_t)s2 * PLANE + cc] = hl;
                }
            }
        }
    }
}

// Writes the four tail regions: h0_T, c0_T, h1_T, c1_T.
__global__ void tail_copy(float* __restrict__ out)
{
    const size_t NP = (size_t)Bn * HIDc * 4096;
    size_t i4 = (size_t)blockIdx.x * blockDim.x + threadIdx.x;
    const size_t N4 = NP / 4;
    if (i4 < N4) {
        const size_t SEQ = Tn * NP;
        float4* o4 = (float4*)out;
        const float4* c0 = (const float4*)g_c0;
        const float4* c1 = (const float4*)g_c1;
        const size_t base = (2 * SEQ) / 4;
        o4[base + 0 * N4 + i4] = o4[((Tn - 1) * NP) / 4 + i4];
        o4[base + 1 * N4 + i4] = c0[i4];
        o4[base + 2 * N4 + i4] = o4[(SEQ + (Tn - 1) * NP) / 4 + i4];
        o4[base + 3 * N4 + i4] = c1[i4];
    }
}

extern "C" void kernel_launch(void* const* d_in, const int* in_sizes, int n_in,
                              void* d_out, int out_size)
{
    const float* x  = (const float*)d_in[0];
    const float* W0 = (const float*)d_in[1];
    const float* b0 = (const float*)d_in[2];
    const float* W1 = (const float*)d_in[3];
    const float* b1 = (const float*)d_in[4];
    float* out = (float*)d_out;

    cudaFuncSetAttribute(step_mma<CINx, 0>,
                         cudaFuncAttributeMaxDynamicSharedMemorySize, SMEM_DYN);
    cudaFuncSetAttribute(step_mma<HIDc, 1>,
                         cudaFuncAttributeMaxDynamicSharedMemorySize, SMEM_DYN);

    const size_t HS = (size_t)Bn * HIDc * 4096;
    float* hseq0 = out;
    float* hseq1 = out + (size_t)Tn * HS;

    // prepasses (deterministic each replay)
    {
        const size_t NX = (size_t)Tn * Bn * CINx * 4096;
        build_x_planes<<<(unsigned)((NX + 255) / 256), 256>>>(x);
        split_w_kernel<0><<<(448 * 128 + 255) / 256, 256>>>(W0);
        split_w_kernel<1><<<(576 * 128 + 255) / 256, 256>>>(W1);
    }

    dim3 grid(32, Bn, 2);
    for (int t = 0; t < Tn; t++) {
        step_mma<CINx, 0><<<grid, 256, SMEM_DYN>>>(b0, hseq0 + (size_t)t * HS, t);
        step_mma<HIDc, 1><<<grid, 256, SMEM_DYN>>>(b1, hseq1 + (size_t)t * HS, t);
    }
    tail_copy<<<(unsigned)((HS / 4 + 255) / 256), 256>>>(out);
}

// round 16
// speedup vs baseline: 1.4839x; 1.4839x over previous
#include <cuda_runtime.h>
#include <cuda_bf16.h>
#include <cstdint>

#define Hdim 64
#define Wdim 64
#define Bn   8
#define HIDc 32
#define Tn   16
#define CINx 16

#define PLANE 4224        // 66 rows x 64 bf16 per shifted plane

using u32 = unsigned int;
using u64 = unsigned long long;

// ---------------- persistent device scratch (no allocation) ----------------
__device__ float g_c0[(size_t)Bn * HIDc * 4096];
__device__ float g_c1[(size_t)Bn * HIDc * 4096];
// x input: [T*B*CIN][3 shifts][66][64] bf16, hi and lo planes.
__device__ __align__(128) __nv_bfloat16 g_xph[(size_t)Tn * Bn * CINx * 3 * PLANE];
__device__ __align__(128) __nv_bfloat16 g_xpl[(size_t)Tn * Bn * CINx * 3 * PLANE];
// hidden states: [parity][B*HID][3][66][64]
__device__ __align__(128) __nv_bfloat16 g_h0ph[2][(size_t)Bn * HIDc * 3 * PLANE];
__device__ __align__(128) __nv_bfloat16 g_h0pl[2][(size_t)Bn * HIDc * 3 * PLANE];
__device__ __align__(128) __nv_bfloat16 g_h1ph[2][(size_t)Bn * HIDc * 3 * PLANE];
__device__ __align__(128) __nv_bfloat16 g_h1pl[2][(size_t)Bn * HIDc * 3 * PLANE];
// weights [k][n] gate-interleaved, hi/lo, PRE-SWIZZLED (seg ^= k&7 within 256B rows)
__device__ __align__(128) __nv_bfloat16 g_w0h[448 * 128], g_w0l[448 * 128];
__device__ __align__(128) __nv_bfloat16 g_w1h[576 * 128], g_w1l[576 * 128];
// permanently-zero 512B source for padded/t0 windows (device globals are zero-init).
__device__ __align__(128) __nv_bfloat16 g_zero[256];

__device__ __forceinline__ float sigm(float v) {
    return __fdividef(1.0f, 1.0f + __expf(-v));
}
__device__ __forceinline__ float tanh_fast(float v) {
    return 2.0f * sigm(2.0f * v) - 1.0f;
}
__device__ __forceinline__ u32 smem_u32(const void* p) {
    u32 a;
    asm("{ .reg .u64 t; cvta.to.shared.u64 t, %1; cvt.u32.u64 %0, t; }"
        : "=r"(a) : "l"(p));
    return a;
}
__device__ __forceinline__ void ldsm4t(u32* r, u32 addr) {
    asm volatile("ldmatrix.sync.aligned.m8n8.x4.trans.shared.b16 {%0,%1,%2,%3}, [%4];"
                 : "=r"(r[0]), "=r"(r[1]), "=r"(r[2]), "=r"(r[3]) : "r"(addr));
}
__device__ __forceinline__ void mma16816(float* d, const u32* a, const u32* b) {
    asm volatile(
        "mma.sync.aligned.m16n8k16.row.col.f32.bf16.bf16.f32 "
        "{%0,%1,%2,%3}, {%4,%5,%6,%7}, {%8,%9}, {%0,%1,%2,%3};"
        : "+f"(d[0]), "+f"(d[1]), "+f"(d[2]), "+f"(d[3])
        : "r"(a[0]), "r"(a[1]), "r"(a[2]), "r"(a[3]), "r"(b[0]), "r"(b[1]));
}
__device__ __forceinline__ void bulkN(u32 dst, const void* src, u32 bytes, u32 mbar) {
    asm volatile(
        "cp.async.bulk.shared::cta.global.mbarrier::complete_tx::bytes [%0], [%1], %2, [%3];"
        :: "r"(dst), "l"(src), "r"(bytes), "r"(mbar) : "memory");
}
__device__ __forceinline__ void mbar_arrive_tx(u32 mbar, u32 bytes) {
    asm volatile("mbarrier.arrive.expect_tx.shared::cta.b64 _, [%0], %1;"
                 :: "r"(mbar), "r"(bytes) : "memory");
}
__device__ __forceinline__ void mbar_wait(u32 addr, u32 parity) {
    asm volatile(
        "{\n\t.reg .pred P;\n\t"
        "W%=:\n\t"
        "mbarrier.try_wait.parity.acquire.cta.shared::cta.b64 P, [%0], %1, 0x989680;\n\t"
        "@!P bra W%=;\n\t}"
        :: "r"(addr), "r"(parity) : "memory");
}

// ---------------- prepass kernels ----------------
__global__ void build_x_planes(const float* __restrict__ x)
{
    size_t i = (size_t)blockIdx.x * blockDim.x + threadIdx.x;
    const size_t N = (size_t)Tn * Bn * CINx * 4096;
    if (i >= N) return;
    const size_t pi = i >> 12;           // (t*B+b)*CIN+ci
    const int px = (int)(i & 4095);
    const int y = px >> 6, xx = px & 63;
    const float v = x[i];
    const __nv_bfloat16 hh = __float2bfloat16(v);
    const __nv_bfloat16 hl = __float2bfloat16(v - __bfloat162float(hh));
    const size_t base = pi * 3 * PLANE + (size_t)(y + 1) * 64;
#pragma unroll
    for (int s = 0; s < 3; s++) {
        const int c = xx + 1 - s;
        if (c >= 0 && c < 64) {
            g_xph[base + (size_t)s * PLANE + c] = hh;
            g_xpl[base + (size_t)s * PLANE + c] = hl;
        }
    }
}

// Weights written swizzled: elem index = k*128 + ((n>>3)^(k&7))*8 + (n&7)
template<int LAYER>
__global__ void split_w_kernel(const float* __restrict__ Wt)
{
    constexpr int KLOG = (LAYER ? (HIDc + HIDc) : (CINx + HIDc)) * 9;   // 576 / 432
    constexpr int KPAD = LAYER ? 576 : 448;
    __nv_bfloat16* wh = LAYER ? g_w1h : g_w0h;
    __nv_bfloat16* wl = LAYER ? g_w1l : g_w0l;
    int idx = blockIdx.x * blockDim.x + threadIdx.x;
    if (idx < KPAD * 128) {
        int k = idx >> 7, n = idx & 127;
        int oc = (n & 3) * HIDc + (n >> 2);      // n = hc*4 + gate
        float v = (k < KLOG) ? Wt[(size_t)oc * KLOG + k] : 0.0f;
        __nv_bfloat16 h = __float2bfloat16(v);
        int out = k * 128 + (((n >> 3) ^ (k & 7)) << 3) + (n & 7);
        wh[out] = h;
        wl[out] = __float2bfloat16(v - __bfloat162float(h));
    }
}

// ---------------- main step kernel ----------------
#define WSTR  528                 // bytes per A window slot (512 data + 16 skew)
#define AHALF (15 * WSTR)         // 7920 B per A tile (hi or lo)
#define BHALF 8192                // 32 k-rows x 256B, contiguous (swizzled)
#define BUFB  (2 * AHALF + 2 * BHALF)   // 32224 B
#define NBUF  2
#define SMEM_DYN (NBUF * BUFB)          // 64448 B

// Buffer layout: [Ah windows][Al windows][Bh][Bl]
template<int CIN_X, int LAYER>
__global__ __launch_bounds__(256, 2)
void step_mma(const float* __restrict__ bias,
              float* __restrict__ h_out,     // fp32 h_seq slab for this t
              int t)
{
    constexpr int CIN_TOT = CIN_X + HIDc;
    constexpr int KLOG = CIN_TOT * 9;
    constexpr int NCH  = (KLOG + 31) / 32;    // 14 / 18

    extern __shared__ __align__(128) u32 dsm[];
    __shared__ float sb[128];
    __shared__ __align__(8) u64 s_mbar[NBUF];

    const int tid = threadIdx.x;
    const int l = tid & 31;
    const int w = tid >> 5;
    const int b = blockIdx.y;
    const int y0 = blockIdx.x * 2;
    const int t0 = (t == 0);
    float* c_state = LAYER ? g_c1 : g_c0;
    __nv_bfloat16* hph = LAYER ? g_h1ph[t & 1] : g_h0ph[t & 1];
    __nv_bfloat16* hpl = LAYER ? g_h1pl[t & 1] : g_h0pl[t & 1];

    if (tid < 128) {
        const int hc = tid >> 2, g = tid & 3;
        sb[tid] = bias[g * HIDc + hc];
    }
    u32 mb[NBUF];
#pragma unroll
    for (int s = 0; s < NBUF; s++) mb[s] = smem_u32(&s_mbar[s]);
    if (tid == 0) {
#pragma unroll
        for (int s = 0; s < NBUF; s++)
            asm volatile("mbarrier.init.shared.b64 [%0], 32;" :: "r"(mb[s]) : "memory");
    }
    __syncthreads();

    // warp tile: wm in {0,32,64,96}, wn in {0,64}
    const int wm = (w & 3) * 32;
    const int wn = (w >> 2) * 64;

    const u32 smb = smem_u32(dsm);

    float acc[2][8][4];
#pragma unroll
    for (int mi = 0; mi < 2; mi++)
#pragma unroll
        for (int ni = 0; ni < 8; ni++)
#pragma unroll
            for (int q = 0; q < 4; q++) acc[mi][ni][q] = 0.0f;

    // ---------------- staging: 30x512B (A windows) + 2x8KB (B) per chunk ------
    auto stage = [&](int ch, int buf) {
        if (tid >= 32) return;
        const u32 mbar = mb[buf];
        if (tid < 30) {
            const int widx = tid >> 1;       // 0..14: ci_local*3 + s
            const int tsel = tid & 1;        // 0 = hi, 1 = lo
            const int ci_base = (ch * 32) / 9;
            const int cl = widx / 3;
            const int s = widx - cl * 3;
            const int ci = ci_base + cl;
            bool zero = (ci >= CIN_TOT);
            const __nv_bfloat16* plane = g_zero;
            if (!zero) {
                if (LAYER == 0) {
                    if (ci < CIN_X) {
                        plane = (tsel ? g_xpl : g_xph) +
                                ((size_t)((t * Bn + b) * CINx + ci) * 3 + s) * PLANE;
                    } else {
                        if (t0) zero = true;
                        else plane = (tsel ? g_h0pl[(t + 1) & 1] : g_h0ph[(t + 1) & 1]) +
                                     ((size_t)(b * HIDc + (ci - CIN_X)) * 3 + s) * PLANE;
                    }
                } else {
                    if (ci < HIDc) {
                        plane = (tsel ? g_h0pl[t & 1] : g_h0ph[t & 1]) +
                                ((size_t)(b * HIDc + ci) * 3 + s) * PLANE;
                    } else {
                        if (t0) zero = true;
                        else plane = (tsel ? g_h1pl[(t + 1) & 1] : g_h1ph[(t + 1) & 1]) +
                                     ((size_t)(b * HIDc + (ci - HIDc)) * 3 + s) * PLANE;
                    }
                }
            }
            const __nv_bfloat16* src = zero ? g_zero : (plane + (size_t)y0 * 64);
            const u32 dst = smb + (u32)(buf * BUFB + tsel * AHALF + widx * WSTR);
            mbar_arrive_tx(mbar, 512);
            bulkN(dst, src, 512, mbar);
        } else {
            const int tsel = tid - 30;       // 0 = hi, 1 = lo
            const __nv_bfloat16* wp = LAYER ? (tsel ? g_w1l : g_w1h)
                                            : (tsel ? g_w0l : g_w0h);
            const __nv_bfloat16* src = wp + (size_t)(ch * 32) * 128;
            const u32 dst = smb + (u32)(buf * BUFB + 2 * AHALF + tsel * BHALF);
            mbar_arrive_tx(mbar, 8192);
            bulkN(dst, src, 8192, mbar);
        }
    };

    // ---------------- compute: fragment-reuse split passes ----------------
    const int krow = (l & 7) + ((l >> 4) & 1) * 8;
    const u32 pxsel = (u32)(((l >> 3) & 1) * 16);
    const u32 brow = (u32)((l & 7) + ((l >> 3) & 1) * 8);
    const u32 bsw = brow & 7;

    auto compute = [&](int buf, int ch) {
        const int ci_base = (ch * 32) / 9;
        const u32 base = smb + (u32)(buf * BUFB);
        const u32 AhB = base;
        const u32 AlB = base + AHALF;
        const u32 BhB = base + 2 * AHALF;
        const u32 BlB = BhB + BHALF;
#pragma unroll
        for (int k16 = 0; k16 < 2; k16++) {
            // per-lane A k-row address
            const int k = ch * 32 + k16 * 16 + krow;
            const int ci = k / 9;
            const int rem = k - ci * 9;
            const int ky = rem / 3;
            const int s = rem - ky * 3;
            const u32 rowoff =
                (u32)(((ci - ci_base) * 3 + s) * WSTR + ky * 128) + pxsel;
            const u32 kofB = (u32)(k16 * 16 * 256);

            u32 ah0[4], ah1[4], al0[4], al1[4];
            ldsm4t(ah0, AhB + rowoff + (u32)(wm * 2));
            ldsm4t(ah1, AhB + rowoff + (u32)((wm + 16) * 2));
            ldsm4t(al0, AlB + rowoff + (u32)(wm * 2));
            ldsm4t(al1, AlB + rowoff + (u32)((wm + 16) * 2));
            u32 bb[16];
#pragma unroll
            for (int q = 0; q < 4; q++) {
                const u32 seg = (u32)((wn >> 3) + 2 * q) + ((u32)(l >> 4) & 1u);
                ldsm4t(bb + q * 4, BhB + kofB + brow * 256 + ((seg ^ bsw) << 4));
            }
#pragma unroll
            for (int ni = 0; ni < 8; ni++) {
                const u32* bf = &bb[(ni >> 1) * 4 + (ni & 1) * 2];
                mma16816(acc[0][ni], ah0, bf);
                mma16816(acc[1][ni], ah1, bf);
            }
#pragma unroll
            for (int ni = 0; ni < 8; ni++) {
                const u32* bf = &bb[(ni >> 1) * 4 + (ni & 1) * 2];
                mma16816(acc[0][ni], al0, bf);
                mma16816(acc[1][ni], al1, bf);
            }
#pragma unroll
            for (int q = 0; q < 4; q++) {
                const u32 seg = (u32)((wn >> 3) + 2 * q) + ((u32)(l >> 4) & 1u);
                ldsm4t(bb + q * 4, BlB + kofB + brow * 256 + ((seg ^ bsw) << 4));
            }
#pragma unroll
            for (int ni = 0; ni < 8; ni++) {
                const u32* bf = &bb[(ni >> 1) * 4 + (ni & 1) * 2];
                mma16816(acc[0][ni], ah0, bf);
                mma16816(acc[1][ni], ah1, bf);
            }
        }
    };

    // ---------------- pipelined chunk loop (R13 structure) ----------------
    int ph[NBUF] = {0, 0};
    stage(0, 0);
    for (int c = 0; c < NCH; c++) {
        __syncthreads();                       // all warps done with buf (c+1)&1
        if (c + 1 < NCH) stage(c + 1, (c + 1) & 1);
        const int s = c & 1;
        mbar_wait(mb[s], ph[s]);
        ph[s] ^= 1;
        compute(s, c);
    }

    // ---------------- epilogue: gate math + h plane writes (validated) -------
    const int tig = l & 3;
    const int rr = l >> 2;
#pragma unroll
    for (int mi = 0; mi < 2; mi++) {
#pragma unroll
        for (int ni = 0; ni < 8; ni++) {
            float* d = acc[mi][ni];
            const float s0 = (tig & 1) ? d[0] : d[2];
            const float s1 = (tig & 1) ? d[1] : d[3];
            const float r0 = __shfl_xor_sync(0xffffffffu, s0, 1);
            const float r1 = __shfl_xor_sync(0xffffffffu, s1, 1);
            float iv, fv, ov, gv;
            int px;
            if (tig & 1) { iv = r0; fv = r1; ov = d[2]; gv = d[3]; px = wm + mi * 16 + rr + 8; }
            else         { iv = d[0]; fv = d[1]; ov = r0; gv = r1; px = wm + mi * 16 + rr; }
            const int hc = ((wn + ni * 8) >> 2) + (tig >> 1);
            iv += sb[hc * 4 + 0];
            fv += sb[hc * 4 + 1];
            ov += sb[hc * 4 + 2];
            gv += sb[hc * 4 + 3];
            const int yy = y0 + (px >> 6);
            const int xx = px & 63;
            const size_t off = (((size_t)b * HIDc + hc) * Hdim + yy) * Wdim + xx;
            const float cp = t0 ? 0.0f : c_state[off];
            const float cn = sigm(fv) * cp + sigm(iv) * tanh_fast(gv);
            const float hn = sigm(ov) * tanh_fast(cn);
            c_state[off] = cn;
            h_out[off] = hn;
            const __nv_bfloat16 hh = __float2bfloat16(hn);
            const __nv_bfloat16 hl = __float2bfloat16(hn - __bfloat162float(hh));
            const size_t pb = (size_t)(b * HIDc + hc) * 3 * PLANE + (size_t)(yy + 1) * 64;
#pragma unroll
            for (int s2 = 0; s2 < 3; s2++) {
                const int cc = xx + 1 - s2;
                if (cc >= 0 && cc < 64) {
                    hph[pb + (size_t)s2 * PLANE + cc] = hh;
                    hpl[pb + (size_t)s2 * PLANE + cc] = hl;
                }
            }
        }
    }
}

// Writes the four tail regions: h0_T, c0_T, h1_T, c1_T.
__global__ void tail_copy(float* __restrict__ out)
{
    const size_t NP = (size_t)Bn * HIDc * 4096;
    size_t i4 = (size_t)blockIdx.x * blockDim.x + threadIdx.x;
    const size_t N4 = NP / 4;
    if (i4 < N4) {
        const size_t SEQ = Tn * NP;
        float4* o4 = (float4*)out;
        const float4* c0 = (const float4*)g_c0;
        const float4* c1 = (const float4*)g_c1;
        const size_t base = (2 * SEQ) / 4;
        o4[base + 0 * N4 + i4] = o4[((Tn - 1) * NP) / 4 + i4];
        o4[base + 1 * N4 + i4] = c0[i4];
        o4[base + 2 * N4 + i4] = o4[(SEQ + (Tn - 1) * NP) / 4 + i4];
        o4[base + 3 * N4 + i4] = c1[i4];
    }
}

extern "C" void kernel_launch(void* const* d_in, const int* in_sizes, int n_in,
                              void* d_out, int out_size)
{
    const float* x  = (const float*)d_in[0];
    const float* W0 = (const float*)d_in[1];
    const float* b0 = (const float*)d_in[2];
    const float* W1 = (const float*)d_in[3];
    const float* b1 = (const float*)d_in[4];
    float* out = (float*)d_out;

    cudaFuncSetAttribute(step_mma<CINx, 0>,
                         cudaFuncAttributeMaxDynamicSharedMemorySize, SMEM_DYN);
    cudaFuncSetAttribute(step_mma<HIDc, 1>,
                         cudaFuncAttributeMaxDynamicSharedMemorySize, SMEM_DYN);

    const size_t HS = (size_t)Bn * HIDc * 4096;
    float* hseq0 = out;
    float* hseq1 = out + (size_t)Tn * HS;

    // prepasses (deterministic each replay)
    {
        const size_t NX = (size_t)Tn * Bn * CINx * 4096;
        build_x_planes<<<(unsigned)((NX + 255) / 256), 256>>>(x);
        split_w_kernel<0><<<(448 * 128 + 255) / 256, 256>>>(W0);
        split_w_kernel<1><<<(576 * 128 + 255) / 256, 256>>>(W1);
    }

    dim3 grid(32, Bn);
    for (int t = 0; t < Tn; t++) {
        step_mma<CINx, 0><<<grid, 256, SMEM_DYN>>>(b0, hseq0 + (size_t)t * HS, t);
        step_mma<HIDc, 1><<<grid, 256, SMEM_DYN>>>(b1, hseq1 + (size_t)t * HS, t);
    }
    tail_copy<<<(unsigned)((HS / 4 + 255) / 256), 256>>>(out);
}